// round 15
// baseline (speedup 1.0000x reference)
#include <cuda_runtime.h>
#include <cuda_bf16.h>
#include <cstdint>

// ----------------------------------------------------------------------------
// CrossAttention, Round 13:
//   - GEMM re-tiled 128x128, warps 2m x 4n (warp tile 64x32): LDSM4:MMA ratio
//     improves 1.5:1 -> 4:1 (2.7x less smem-pipe traffic per FLOP).
//   - Wp pre-split into g_qh/g_ql (dead after attention): proj B staging is
//     now a pure copy too; the scalar-STS fp32-W path is gone.
//   - attention unchanged. Statics unchanged: 62,914,560 B (arena-safe).
// ----------------------------------------------------------------------------

#define NB    2
#define NSEQ  1024
#define DIM   768
#define NH    12
#define DH    64
#define QSCALE 0.125f

#define MTOT  (NB*NSEQ)
#define NQKV  (3*DIM)
#define KDIM  DIM
#define KC    32
#define NCH   (KDIM/KC)

#define QKV_ELEMS (2*NB*NH*NSEQ*DH)
__device__ __align__(16) __nv_bfloat16 g_qh[QKV_ELEMS];  // [s][b][h][n][d], scaled
__device__ __align__(16) __nv_bfloat16 g_ql[QKV_ELEMS];
__device__ __align__(16) __nv_bfloat16 g_kh[QKV_ELEMS];  // [s][b][h][n][d]
__device__ __align__(16) __nv_bfloat16 g_kl[QKV_ELEMS];
__device__ __align__(16) __nv_bfloat16 g_vh[QKV_ELEMS];  // [s][b][h][d][n]
__device__ __align__(16) __nv_bfloat16 g_vl[QKV_ELEMS];
__device__ __align__(16) float g_attn[4*NB*NSEQ*DIM];
// g_attn doubles as pre-QKV scratch for split Wqkv (14.16MB < 25.17MB).
// g_qh/g_ql double as post-attention scratch for split Wp (2.36MB < 6.29MB).
#define WSPLIT_ELEMS (2*NQKV*KDIM)

// ============================ helpers =======================================
__device__ __forceinline__ uint32_t s2u(const void* p) {
    uint32_t a;
    asm("{ .reg .u64 t; cvta.to.shared.u64 t, %1; cvt.u32.u64 %0, t; }"
        : "=r"(a) : "l"(p));
    return a;
}

#define MMA16816(d0,d1,d2,d3,a0,a1,a2,a3,b0,b1)                               \
    asm volatile(                                                             \
        "mma.sync.aligned.m16n8k16.row.col.f32.bf16.bf16.f32 "                \
        "{%0,%1,%2,%3}, {%4,%5,%6,%7}, {%8,%9}, {%0,%1,%2,%3};"               \
        : "+f"(d0), "+f"(d1), "+f"(d2), "+f"(d3)                              \
        : "r"(a0), "r"(a1), "r"(a2), "r"(a3), "r"(b0), "r"(b1))

#define LDSM4(r0,r1,r2,r3,addr)                                               \
    asm volatile("ldmatrix.sync.aligned.m8n8.x4.shared.b16 {%0,%1,%2,%3}, [%4];" \
        : "=r"(r0), "=r"(r1), "=r"(r2), "=r"(r3) : "r"(addr))

__device__ __forceinline__ void split2(float v, __nv_bfloat16& h, __nv_bfloat16& l) {
    h = __float2bfloat16_rn(v);
    l = __float2bfloat16_rn(v - __bfloat162float(h));
}

__device__ __forceinline__ void splitpack2(float x, float y,
                                           uint32_t& hp, uint32_t& lp) {
    __nv_bfloat16 hx = __float2bfloat16_rn(x);
    __nv_bfloat16 hy = __float2bfloat16_rn(y);
    __nv_bfloat16 lx = __float2bfloat16_rn(x - __bfloat162float(hx));
    __nv_bfloat16 ly = __float2bfloat16_rn(y - __bfloat162float(hy));
    hp = (uint32_t)__bfloat16_as_ushort(hx) | ((uint32_t)__bfloat16_as_ushort(hy) << 16);
    lp = (uint32_t)__bfloat16_as_ushort(lx) | ((uint32_t)__bfloat16_as_ushort(ly) << 16);
}

__device__ __forceinline__ float fexp(float x) {
    x = fmaxf(x, -87.0f);
    float y = x * 1.4426950408889634f;
    float t = y + 12582912.0f;
    int   n = __float_as_int(t) - 0x4B400000;
    float f = y - (t - 12582912.0f);
    float p = 1.33335581e-3f;
    p = fmaf(p, f, 9.61812911e-3f);
    p = fmaf(p, f, 5.55041086e-2f);
    p = fmaf(p, f, 2.40226512e-1f);
    p = fmaf(p, f, 6.93147182e-1f);
    p = fmaf(p, f, 1.0f);
    float s = __int_as_float((n + 127) << 23);
    return p * s;
}

// ============================ W transpose+split =============================
// which==0: Wqkv [768][2304] -> g_attn scratch bf16 hi/lo [s][2304][768]
// which==1: Wp   [768][768]  -> g_qh/g_ql       bf16 hi/lo [s][768][768]
__global__ void wsplit_kernel(const float* __restrict__ W1,
                              const float* __restrict__ W2, int which)
{
    __shared__ float tile[32][33];
    const int N = which ? DIM : NQKV;
    __nv_bfloat16* wh = which ? g_qh : (__nv_bfloat16*)g_attn;
    __nv_bfloat16* wl = which ? g_ql : ((__nv_bfloat16*)g_attn + WSPLIT_ELEMS);
    const int s = blockIdx.z;
    const float* __restrict__ W = s ? W2 : W1;
    const int n0 = blockIdx.x * 32;
    const int k0 = blockIdx.y * 32;
    const int tx = threadIdx.x, ty = threadIdx.y;
    #pragma unroll
    for (int j = 0; j < 4; j++)
        tile[ty + j * 8][tx] = W[(size_t)(k0 + ty + j * 8) * N + n0 + tx];
    __syncthreads();
    #pragma unroll
    for (int j = 0; j < 4; j++) {
        float v = tile[tx][ty + j * 8];
        __nv_bfloat16 h, l;
        split2(v, h, l);
        size_t o = ((size_t)s * N + n0 + ty + j * 8) * KDIM + k0 + tx;
        wh[o] = h;
        wl[o] = l;
    }
}

// ============================ HMMA GEMM (128x128, 2m x 4n warps) ============
#define ROWB   80
#define OFF_AH 0
#define OFF_AL (128*ROWB)          // 10240
#define OFF_BH (2*128*ROWB)        // 20480
#define OFF_BL (3*128*ROWB)        // 30720
#define STAGEB (4*128*ROWB)        // 40960
#define GEMM_SMEM (2*STAGEB)       // 81920
#define HLOFF  10240               // hi -> lo region offset

#define DECL_ACC(mt,nt) \
    float c##mt##nt##0 = 0.f, c##mt##nt##1 = 0.f, c##mt##nt##2 = 0.f, c##mt##nt##3 = 0.f

#define MMA3(mt,nt) \
    MMA16816(c##mt##nt##0, c##mt##nt##1, c##mt##nt##2, c##mt##nt##3,          \
             ah0, ah1, ah2, ah3, bh##nt##0, bh##nt##1);                       \
    MMA16816(c##mt##nt##0, c##mt##nt##1, c##mt##nt##2, c##mt##nt##3,          \
             ah0, ah1, ah2, ah3, bl##nt##0, bl##nt##1);                       \
    MMA16816(c##mt##nt##0, c##mt##nt##1, c##mt##nt##2, c##mt##nt##3,          \
             al0, al1, al2, al3, bh##nt##0, bh##nt##1)

#define MMA_MT(mt) do {                                                       \
    uint32_t ah0, ah1, ah2, ah3, al0, al1, al2, al3;                          \
    LDSM4(ah0, ah1, ah2, ah3, aA0 + (mt) * (16 * ROWB) + ko);                 \
    LDSM4(al0, al1, al2, al3, aA0 + (mt) * (16 * ROWB) + ko + HLOFF);         \
    MMA3(mt,0); MMA3(mt,1); MMA3(mt,2); MMA3(mt,3);                           \
} while (0)

#define EPILOG(mt,nt) do {                                                    \
    const int row0 = m0 + wm * 64 + (mt) * 16 + g;                            \
    const int colg = n0 + wn * 32 + (nt) * 8 + 2 * tg;                        \
    const float e0 = c##mt##nt##0, e1 = c##mt##nt##1;                         \
    const float e2 = c##mt##nt##2, e3 = c##mt##nt##3;                         \
    if (mode == 0) {                                                          \
        const int t3  = colg / DIM;                                           \
        const int rem = colg - t3 * DIM;                                      \
        const int h   = rem >> 6;                                             \
        const int d0  = rem & 63;                                             \
        const int m1_ = row0,     b1_ = m1_ >> 10, nq1 = m1_ & (NSEQ - 1);    \
        const int m2_ = row0 + 8, b2_ = m2_ >> 10, nq2 = m2_ & (NSEQ - 1);    \
        if (t3 == 2) {                                                        \
            const size_t vb1 = (((size_t)(s * NB + b1_) * NH + h) * DH + d0) * NSEQ + nq1; \
            const size_t vb2 = (((size_t)(s * NB + b2_) * NH + h) * DH + d0) * NSEQ + nq2; \
            __nv_bfloat16 h_, l_;                                             \
            split2(e0, h_, l_); g_vh[vb1] = h_;        g_vl[vb1] = l_;        \
            split2(e1, h_, l_); g_vh[vb1 + NSEQ] = h_; g_vl[vb1 + NSEQ] = l_; \
            split2(e2, h_, l_); g_vh[vb2] = h_;        g_vl[vb2] = l_;        \
            split2(e3, h_, l_); g_vh[vb2 + NSEQ] = h_; g_vl[vb2 + NSEQ] = l_; \
        } else {                                                              \
            const float sc_ = (t3 == 0) ? QSCALE : 1.0f;                      \
            __nv_bfloat16* dh = (t3 == 0) ? g_qh : g_kh;                      \
            __nv_bfloat16* dl = (t3 == 0) ? g_ql : g_kl;                      \
            uint32_t hp_, lp_;                                                \
            const size_t i1 = ((((size_t)(s * NB + b1_) * NH + h) * NSEQ + nq1) * DH + d0); \
            const size_t i2 = ((((size_t)(s * NB + b2_) * NH + h) * NSEQ + nq2) * DH + d0); \
            splitpack2(e0 * sc_, e1 * sc_, hp_, lp_);                         \
            *(uint32_t*)(dh + i1) = hp_; *(uint32_t*)(dl + i1) = lp_;         \
            splitpack2(e2 * sc_, e3 * sc_, hp_, lp_);                         \
            *(uint32_t*)(dh + i2) = hp_; *(uint32_t*)(dl + i2) = lp_;         \
        }                                                                     \
    } else {                                                                  \
        const float* bias = s ? bias2 : bias1;                                \
        const float bx = bias[colg], by = bias[colg + 1];                     \
        *(float2*)(out + ((size_t)s * MTOT + row0) * DIM + colg)              \
            = make_float2(e0 + bx, e1 + by);                                  \
        *(float2*)(out + ((size_t)s * MTOT + row0 + 8) * DIM + colg)          \
            = make_float2(e2 + bx, e3 + by);                                  \
    }                                                                         \
} while (0)

#define STAGE_LOAD_A(cc) do {                                                 \
    const float* _p = pA0 + (cc) * KC;                                        \
    _Pragma("unroll")                                                         \
    for (int i4 = 0; i4 < 4; i4++) {                                          \
        float4 v = *(const float4*)(_p + i4 * 4);                             \
        if (mode == 1) {                                                      \
            float4 w = *(const float4*)(pA1 + (cc) * KC + i4 * 4);            \
            v.x += w.x; v.y += w.y; v.z += w.z; v.w += w.w;                   \
        }                                                                     \
        ar[i4 * 4 + 0] = v.x; ar[i4 * 4 + 1] = v.y;                           \
        ar[i4 * 4 + 2] = v.z; ar[i4 * 4 + 3] = v.w;                           \
    }                                                                         \
} while (0)

#define STAGE_LOAD_B(cc) do {                                                 \
    b4h0 = *(const uint4*)(pBh + (cc) * KC);                                  \
    b4h1 = *(const uint4*)(pBh + (cc) * KC + 8);                              \
    b4l0 = *(const uint4*)(pBl + (cc) * KC);                                  \
    b4l1 = *(const uint4*)(pBl + (cc) * KC + 8);                              \
} while (0)

__global__ void __launch_bounds__(256, 1) hmma_gemm_kernel(
    const float* __restrict__ A1g, const float* __restrict__ A2g,
    int Ntot, int mode,
    const float* __restrict__ bias1, const float* __restrict__ bias2,
    float* __restrict__ out)
{
    extern __shared__ __align__(16) char smc[];
    const uint32_t sb = s2u(smc);
    const int tid  = threadIdx.x;
    const int lane = tid & 31;
    const int warp = tid >> 5;
    const int wm   = warp >> 2;        // 0..1
    const int wn   = warp & 3;         // 0..3
    const int g    = lane >> 2;
    const int tg   = lane & 3;
    const int s    = blockIdx.z;
    const int m0   = blockIdx.y * 128;
    const int n0   = blockIdx.x * 128;

    // A staging: 128 rows, 2 thr/row, 16 fp32 each
    const int arow = tid >> 1;
    const int akb  = (tid & 1) * 16;
    const float* pA0;
    const float* pA1 = nullptr;
    if (mode == 0) {
        const float* Ag = s ? A2g : A1g;
        pA0 = Ag + (size_t)(m0 + arow) * KDIM + akb;
    } else {
        const size_t per = (size_t)MTOT * KDIM;
        pA0 = g_attn + (size_t)(2 * s) * per + (size_t)(m0 + arow) * KDIM + akb;
        pA1 = pA0 + per;
    }

    // B staging: pre-split bf16 [s][n][k]; 2 thr/row, 16 elems each
    const int brow = tid >> 1;
    const int bseg = (tid & 1) * 16;
    const __nv_bfloat16* pBh;
    const __nv_bfloat16* pBl;
    if (mode == 0) {
        pBh = (const __nv_bfloat16*)g_attn
            + ((size_t)s * NQKV + n0 + brow) * KDIM + bseg;
        pBl = pBh + WSPLIT_ELEMS;
    } else {
        const size_t o = ((size_t)s * DIM + n0 + brow) * KDIM + bseg;
        pBh = g_qh + o;
        pBl = g_ql + o;
    }

    // ldmatrix lane bases
    const uint32_t aA0 = sb + OFF_AH
        + (uint32_t)((wm * 64 + (lane & 15)) * ROWB + (lane >> 4) * 16);
    const int bro = (lane & 7) + ((lane >> 4) << 3);
    const uint32_t aB0 = sb + OFF_BH
        + (uint32_t)((wn * 32 + bro) * ROWB + ((lane >> 3) & 1) * 16);
    const uint32_t aB1 = aB0 + 16 * ROWB;

    DECL_ACC(0,0); DECL_ACC(0,1); DECL_ACC(0,2); DECL_ACC(0,3);
    DECL_ACC(1,0); DECL_ACC(1,1); DECL_ACC(1,2); DECL_ACC(1,3);
    DECL_ACC(2,0); DECL_ACC(2,1); DECL_ACC(2,2); DECL_ACC(2,3);
    DECL_ACC(3,0); DECL_ACC(3,1); DECL_ACC(3,2); DECL_ACC(3,3);

    float ar[16];
    uint4 b4h0, b4h1, b4l0, b4l1;
    STAGE_LOAD_A(0);
    STAGE_LOAD_B(0);

    for (int c = 0; c < NCH; c++) {
        const uint32_t boff = (uint32_t)((c & 1) * STAGEB);
        {
            char* bufp = smc + (c & 1) * STAGEB;
            char* adst = bufp + arow * ROWB + akb * 2;
            #pragma unroll
            for (int i = 0; i < 8; i++) {
                uint32_t hp, lp;
                splitpack2(ar[2 * i], ar[2 * i + 1], hp, lp);
                *(uint32_t*)(adst + OFF_AH + i * 4) = hp;
                *(uint32_t*)(adst + OFF_AL + i * 4) = lp;
            }
            char* bdst = bufp + brow * ROWB + bseg * 2;
            *(uint4*)(bdst + OFF_BH)      = b4h0;
            *(uint4*)(bdst + OFF_BH + 16) = b4h1;
            *(uint4*)(bdst + OFF_BL)      = b4l0;
            *(uint4*)(bdst + OFF_BL + 16) = b4l1;
        }
        __syncthreads();

        if (c + 1 < NCH) {
            STAGE_LOAD_A(c + 1);
            STAGE_LOAD_B(c + 1);
        }

        #pragma unroll
        for (int kk = 0; kk < 2; kk++) {
            const uint32_t ko = boff + kk * 32;
            uint32_t bh00, bh01, bh10, bh11, bl00, bl01, bl10, bl11;
            uint32_t bh20, bh21, bh30, bh31, bl20, bl21, bl30, bl31;
            LDSM4(bh00, bh01, bh10, bh11, aB0 + ko);
            LDSM4(bl00, bl01, bl10, bl11, aB0 + ko + HLOFF);
            LDSM4(bh20, bh21, bh30, bh31, aB1 + ko);
            LDSM4(bl20, bl21, bl30, bl31, aB1 + ko + HLOFF);
            MMA_MT(0);
            MMA_MT(1);
            MMA_MT(2);
            MMA_MT(3);
        }
    }

    EPILOG(0,0); EPILOG(0,1); EPILOG(0,2); EPILOG(0,3);
    EPILOG(1,0); EPILOG(1,1); EPILOG(1,2); EPILOG(1,3);
    EPILOG(2,0); EPILOG(2,1); EPILOG(2,2); EPILOG(2,3);
    EPILOG(3,0); EPILOG(3,1); EPILOG(3,2); EPILOG(3,3);
}

// ============================ HMMA attention (unchanged R12) ================
#define AROWB  144
#define A_VOFF (2*64*AROWB)
#define A_LOFF (64*AROWB)
#define ATT_SMEM (4*64*AROWB)
#define ATT_SMEM2 (2*ATT_SMEM)

#define LOADQ(ks)                                                             \
    uint32_t qh##ks##0, qh##ks##1, qh##ks##2, qh##ks##3;                      \
    uint32_t ql##ks##0, ql##ks##1, ql##ks##2, ql##ks##3;                      \
    do {                                                                      \
        qh##ks##0 = *(const uint32_t*)(Qh0 + (ks)*16 + 2*tg);                 \
        qh##ks##1 = *(const uint32_t*)(Qh1 + (ks)*16 + 2*tg);                 \
        qh##ks##2 = *(const uint32_t*)(Qh0 + (ks)*16 + 8 + 2*tg);             \
        qh##ks##3 = *(const uint32_t*)(Qh1 + (ks)*16 + 8 + 2*tg);             \
        ql##ks##0 = *(const uint32_t*)(Ql0 + (ks)*16 + 2*tg);                 \
        ql##ks##1 = *(const uint32_t*)(Ql1 + (ks)*16 + 2*tg);                 \
        ql##ks##2 = *(const uint32_t*)(Ql0 + (ks)*16 + 8 + 2*tg);             \
        ql##ks##3 = *(const uint32_t*)(Ql1 + (ks)*16 + 8 + 2*tg);             \
    } while (0)

#define ADECL_S(nt) float s##nt##0=0.f, s##nt##1=0.f, s##nt##2=0.f, s##nt##3=0.f
#define ADECL_O(nt) float o##nt##0=0.f, o##nt##1=0.f, o##nt##2=0.f, o##nt##3=0.f
#define ADECL_P(nt) uint32_t pha##nt=0u, phb##nt=0u, pla##nt=0u, plb##nt=0u

#define ASMMA_P(ks,p,na,nb) do {                                              \
    uint32_t kh0,kh1,kh2,kh3, kl0,kl1,kl2,kl3;                                \
    LDSM4(kh0,kh1,kh2,kh3, aK##p + abuf + (ks)*32);                           \
    LDSM4(kl0,kl1,kl2,kl3, aK##p + abuf + A_LOFF + (ks)*32);                  \
    MMA16816(s##na##0,s##na##1,s##na##2,s##na##3,                             \
             qh##ks##0,qh##ks##1,qh##ks##2,qh##ks##3, kh0,kh1);               \
    MMA16816(s##na##0,s##na##1,s##na##2,s##na##3,                             \
             qh##ks##0,qh##ks##1,qh##ks##2,qh##ks##3, kl0,kl1);               \
    MMA16816(s##na##0,s##na##1,s##na##2,s##na##3,                             \
             ql##ks##0,ql##ks##1,ql##ks##2,ql##ks##3, kh0,kh1);               \
    MMA16816(s##nb##0,s##nb##1,s##nb##2,s##nb##3,                             \
             qh##ks##0,qh##ks##1,qh##ks##2,qh##ks##3, kh2,kh3);               \
    MMA16816(s##nb##0,s##nb##1,s##nb##2,s##nb##3,                             \
             qh##ks##0,qh##ks##1,qh##ks##2,qh##ks##3, kl2,kl3);               \
    MMA16816(s##nb##0,s##nb##1,s##nb##2,s##nb##3,                             \
             ql##ks##0,ql##ks##1,ql##ks##2,ql##ks##3, kh2,kh3);               \
} while (0)

#define ASMMA_ALLNT(ks) do {                                                  \
    ASMMA_P(ks,0,0,1); ASMMA_P(ks,1,2,3);                                     \
    ASMMA_P(ks,2,4,5); ASMMA_P(ks,3,6,7); } while (0)

#define AROWMAX(nt) do {                                                      \
    mxA = fmaxf(mxA, fmaxf(s##nt##0, s##nt##1));                              \
    mxB = fmaxf(mxB, fmaxf(s##nt##2, s##nt##3)); } while (0)

#define ASOFT(nt) do {                                                        \
    const float p0_ = fexp(s##nt##0 - mxA);                                   \
    const float p1_ = fexp(s##nt##1 - mxA);                                   \
    const float p2_ = fexp(s##nt##2 - mxB);                                   \
    const float p3_ = fexp(s##nt##3 - mxB);                                   \
    sumA += p0_ + p1_; sumB += p2_ + p3_;                                     \
    splitpack2(p0_, p1_, pha##nt, pla##nt);                                   \
    splitpack2(p2_, p3_, phb##nt, plb##nt);                                   \
    o##nt##0 *= corrA; o##nt##1 *= corrA;                                     \
    o##nt##2 *= corrB; o##nt##3 *= corrB; } while (0)

#define APV_P(ks,ta,tb,p,na,nb) do {                                          \
    uint32_t vh0,vh1,vh2,vh3, vl0,vl1,vl2,vl3;                                \
    LDSM4(vh0,vh1,vh2,vh3, aV##p + abuf + (ks)*32);                           \
    LDSM4(vl0,vl1,vl2,vl3, aV##p + abuf + A_LOFF + (ks)*32);                  \
    MMA16816(o##na##0,o##na##1,o##na##2,o##na##3,                             \
             pha##ta, phb##ta, pha##tb, phb##tb, vh0,vh1);                    \
    MMA16816(o##na##0,o##na##1,o##na##2,o##na##3,                             \
             pha##ta, phb##ta, pha##tb, phb##tb, vl0,vl1);                    \
    MMA16816(o##na##0,o##na##1,o##na##2,o##na##3,                             \
             pla##ta, plb##ta, pla##tb, plb##tb, vh0,vh1);                    \
    MMA16816(o##nb##0,o##nb##1,o##nb##2,o##nb##3,                             \
             pha##ta, phb##ta, pha##tb, phb##tb, vh2,vh3);                    \
    MMA16816(o##nb##0,o##nb##1,o##nb##2,o##nb##3,                             \
             pha##ta, phb##ta, pha##tb, phb##tb, vl2,vl3);                    \
    MMA16816(o##nb##0,o##nb##1,o##nb##2,o##nb##3,                             \
             pla##ta, plb##ta, pla##tb, plb##tb, vh2,vh3);                    \
} while (0)

#define APVMMA_ALLNT(ks,ta,tb) do {                                           \
    APV_P(ks,ta,tb,0,0,1); APV_P(ks,ta,tb,1,2,3);                             \
    APV_P(ks,ta,tb,2,4,5); APV_P(ks,ta,tb,3,6,7); } while (0)

#define AWRITE(nt) do {                                                       \
    *(float2*)(OgA + (nt)*8 + 2*tg) = make_float2(o##nt##0*invA, o##nt##1*invA); \
    *(float2*)(OgB + (nt)*8 + 2*tg) = make_float2(o##nt##2*invB, o##nt##3*invB); \
} while (0)

__global__ void __launch_bounds__(256, 1) attn_hmma_kernel()
{
    extern __shared__ __align__(16) char smc[];
    const uint32_t sb = s2u(smc);
    const int tid  = threadIdx.x;
    const int lane = tid & 31;
    const int warp = tid >> 5;
    const int g    = lane >> 2;
    const int tg   = lane & 3;
    const int combo = blockIdx.z;
    const int bh    = blockIdx.y;
    const int q0    = blockIdx.x * 128;
    const int qs    = combo >> 1;
    const int kvs   = ((combo + 1) >> 1) & 1;

    const size_t qoff  = ((size_t)(qs  * NB * NH) + bh) * NSEQ * DH;
    const size_t kvoff = ((size_t)(kvs * NB * NH) + bh) * NSEQ * DH;

    const __nv_bfloat16* Qh0 = g_qh + qoff + (size_t)(q0 + warp * 16 + g) * DH;
    const __nv_bfloat16* Qh1 = Qh0 + 8 * DH;
    const __nv_bfloat16* Ql0 = g_ql + qoff + (size_t)(q0 + warp * 16 + g) * DH;
    const __nv_bfloat16* Ql1 = Ql0 + 8 * DH;
    LOADQ(0); LOADQ(1); LOADQ(2); LOADQ(3);

    ADECL_O(0); ADECL_O(1); ADECL_O(2); ADECL_O(3);
    ADECL_O(4); ADECL_O(5); ADECL_O(6); ADECL_O(7);
    float mA = -1e30f, mB = -1e30f, lA = 0.f, lB = 0.f;

    const int srow = tid >> 2;
    const int sel  = (tid & 3) * 16;
    const __nv_bfloat16* pKh = g_kh + kvoff + (size_t)srow * DH + sel;
    const __nv_bfloat16* pKl = g_kl + kvoff + (size_t)srow * DH + sel;
    const __nv_bfloat16* pVh = g_vh + kvoff + (size_t)srow * NSEQ + sel;
    const __nv_bfloat16* pVl = g_vl + kvoff + (size_t)srow * NSEQ + sel;
    char* kds = smc + srow * AROWB + sel * 2;
    char* vds = smc + A_VOFF + srow * AROWB + sel * 2;

    const int bro = (lane & 7) + ((lane >> 4) << 3);
    const uint32_t kb16 = ((lane >> 3) & 1) * 16;
    const uint32_t aK0 = sb + (uint32_t)(bro * AROWB) + kb16;
    const uint32_t aK1 = aK0 + 16 * AROWB;
    const uint32_t aK2 = aK0 + 32 * AROWB;
    const uint32_t aK3 = aK0 + 48 * AROWB;
    const uint32_t aV0 = aK0 + A_VOFF;
    const uint32_t aV1 = aK1 + A_VOFF;
    const uint32_t aV2 = aK2 + A_VOFF;
    const uint32_t aV3 = aK3 + A_VOFF;

    for (int kt = 0; kt < NSEQ / 64; kt++) {
        const int k0 = kt * 64;
        const int ab = (kt & 1) * ATT_SMEM;
        {
            const size_t ko_k = (size_t)k0 * DH;
            uint4 t0 = *(const uint4*)(pKh + ko_k);
            uint4 t1 = *(const uint4*)(pKh + ko_k + 8);
            *(uint4*)(kds + ab)      = t0;
            *(uint4*)(kds + ab + 16) = t1;
            t0 = *(const uint4*)(pKl + ko_k);
            t1 = *(const uint4*)(pKl + ko_k + 8);
            *(uint4*)(kds + ab + A_LOFF)      = t0;
            *(uint4*)(kds + ab + A_LOFF + 16) = t1;
            t0 = *(const uint4*)(pVh + k0);
            t1 = *(const uint4*)(pVh + k0 + 8);
            *(uint4*)(vds + ab)      = t0;
            *(uint4*)(vds + ab + 16) = t1;
            t0 = *(const uint4*)(pVl + k0);
            t1 = *(const uint4*)(pVl + k0 + 8);
            *(uint4*)(vds + ab + A_LOFF)      = t0;
            *(uint4*)(vds + ab + A_LOFF + 16) = t1;
        }
        __syncthreads();
        const uint32_t abuf = (uint32_t)ab;

        ADECL_S(0); ADECL_S(1); ADECL_S(2); ADECL_S(3);
        ADECL_S(4); ADECL_S(5); ADECL_S(6); ADECL_S(7);
        ASMMA_ALLNT(0); ASMMA_ALLNT(1); ASMMA_ALLNT(2); ASMMA_ALLNT(3);

        float mxA = mA, mxB = mB;
        AROWMAX(0); AROWMAX(1); AROWMAX(2); AROWMAX(3);
        AROWMAX(4); AROWMAX(5); AROWMAX(6); AROWMAX(7);
        mxA = fmaxf(mxA, __shfl_xor_sync(0xffffffffu, mxA, 1));
        mxA = fmaxf(mxA, __shfl_xor_sync(0xffffffffu, mxA, 2));
        mxB = fmaxf(mxB, __shfl_xor_sync(0xffffffffu, mxB, 1));
        mxB = fmaxf(mxB, __shfl_xor_sync(0xffffffffu, mxB, 2));
        const float corrA = fexp(mA - mxA);
        const float corrB = fexp(mB - mxB);
        float sumA = 0.f, sumB = 0.f;
        ADECL_P(0); ADECL_P(1); ADECL_P(2); ADECL_P(3);
        ADECL_P(4); ADECL_P(5); ADECL_P(6); ADECL_P(7);
        ASOFT(0); ASOFT(1); ASOFT(2); ASOFT(3);
        ASOFT(4); ASOFT(5); ASOFT(6); ASOFT(7);
        sumA += __shfl_xor_sync(0xffffffffu, sumA, 1);
        sumA += __shfl_xor_sync(0xffffffffu, sumA, 2);
        sumB += __shfl_xor_sync(0xffffffffu, sumB, 1);
        sumB += __shfl_xor_sync(0xffffffffu, sumB, 2);
        lA = lA * corrA + sumA;
        lB = lB * corrB + sumB;
        mA = mxA; mB = mxB;

        APVMMA_ALLNT(0,0,1); APVMMA_ALLNT(1,2,3);
        APVMMA_ALLNT(2,4,5); APVMMA_ALLNT(3,6,7);
    }

    const int b = bh / NH, h = bh - (bh / NH) * NH;
    const int row0 = q0 + warp * 16 + g;
    float* OgA = g_attn + ((size_t)(combo * NB + b) * NSEQ + row0) * DIM + h * DH;
    float* OgB = OgA + 8 * DIM;
    const float invA = 1.f / lA, invB = 1.f / lB;
    AWRITE(0); AWRITE(1); AWRITE(2); AWRITE(3);
    AWRITE(4); AWRITE(5); AWRITE(6); AWRITE(7);
}

// ============================ launch ========================================
extern "C" void kernel_launch(void* const* d_in, const int* in_sizes, int n_in,
                              void* d_out, int out_size)
{
    const float* x1    = (const float*)d_in[0];
    const float* x2    = (const float*)d_in[1];
    const float* Wqkv1 = (const float*)d_in[2];
    const float* Wqkv2 = (const float*)d_in[3];
    const float* Wp1   = (const float*)d_in[4];
    const float* bp1   = (const float*)d_in[5];
    const float* Wp2   = (const float*)d_in[6];
    const float* bp2   = (const float*)d_in[7];
    float* out = (float*)d_out;

    cudaFuncSetAttribute(hmma_gemm_kernel,
                         cudaFuncAttributeMaxDynamicSharedMemorySize, GEMM_SMEM);
    cudaFuncSetAttribute(attn_hmma_kernel,
                         cudaFuncAttributeMaxDynamicSharedMemorySize, ATT_SMEM2);

    // pre-split Wqkv into g_attn scratch (dead until attention)
    wsplit_kernel<<<dim3(NQKV / 32, KDIM / 32, 2), dim3(32, 8)>>>(Wqkv1, Wqkv2, 0);

    hmma_gemm_kernel<<<dim3(NQKV / 128, MTOT / 128, 2), 256, GEMM_SMEM>>>(
        x1, x2, NQKV, 0, nullptr, nullptr, nullptr);

    attn_hmma_kernel<<<dim3(8, 24, 4), 256, ATT_SMEM2>>>();

    // pre-split Wp into g_qh/g_ql (dead after attention)
    wsplit_kernel<<<dim3(DIM / 32, KDIM / 32, 2), dim3(32, 8)>>>(Wp1, Wp2, 1);

    hmma_gemm_kernel<<<dim3(DIM / 128, MTOT / 128, 2), 256, GEMM_SMEM>>>(
        nullptr, nullptr, DIM, 1, bp1, bp2, out);
}

// round 17
// speedup vs baseline: 1.1910x; 1.1910x over previous
#include <cuda_runtime.h>
#include <cuda_bf16.h>
#include <cstdint>

// ----------------------------------------------------------------------------
// CrossAttention, Round 14 (resubmitted verbatim after infra failure):
//   - attention: cp.async KV staging with cross-tile prefetch (overlaps global
//     latency with compute; was fully serial per tile), exp2-domain softmax
//     (log2e baked into pre-split Q), fast single-cvt bf16x2 splitpack.
//   - GEMM: B staging via cp.async (frees prefetch regs -> 2 CTAs/SM).
//   Statics unchanged: 62,914,560 B (arena-safe).
// ----------------------------------------------------------------------------

#define NB    2
#define NSEQ  1024
#define DIM   768
#define NH    12
#define DH    64
#define QSCALE 0.125f
#define QSC2  0.18033688011112042f   // QSCALE * log2(e)

#define MTOT  (NB*NSEQ)
#define NQKV  (3*DIM)
#define KDIM  DIM
#define KC    32
#define NCH   (KDIM/KC)

#define QKV_ELEMS (2*NB*NH*NSEQ*DH)
__device__ __align__(16) __nv_bfloat16 g_qh[QKV_ELEMS];  // [s][b][h][n][d], x QSC2
__device__ __align__(16) __nv_bfloat16 g_ql[QKV_ELEMS];
__device__ __align__(16) __nv_bfloat16 g_kh[QKV_ELEMS];  // [s][b][h][n][d]
__device__ __align__(16) __nv_bfloat16 g_kl[QKV_ELEMS];
__device__ __align__(16) __nv_bfloat16 g_vh[QKV_ELEMS];  // [s][b][h][d][n]
__device__ __align__(16) __nv_bfloat16 g_vl[QKV_ELEMS];
__device__ __align__(16) float g_attn[4*NB*NSEQ*DIM];
#define WSPLIT_ELEMS (2*NQKV*KDIM)

// ============================ helpers =======================================
__device__ __forceinline__ uint32_t s2u(const void* p) {
    uint32_t a;
    asm("{ .reg .u64 t; cvta.to.shared.u64 t, %1; cvt.u32.u64 %0, t; }"
        : "=r"(a) : "l"(p));
    return a;
}

__device__ __forceinline__ void cpasync16(uint32_t saddr, const void* g) {
    asm volatile("cp.async.ca.shared.global [%0], [%1], 16;"
                 :: "r"(saddr), "l"(g) : "memory");
}
#define CP_COMMIT() asm volatile("cp.async.commit_group;" ::: "memory")
#define CP_WAIT(n)  asm volatile("cp.async.wait_group %0;" :: "n"(n) : "memory")

#define MMA16816(d0,d1,d2,d3,a0,a1,a2,a3,b0,b1)                               \
    asm volatile(                                                             \
        "mma.sync.aligned.m16n8k16.row.col.f32.bf16.bf16.f32 "                \
        "{%0,%1,%2,%3}, {%4,%5,%6,%7}, {%8,%9}, {%0,%1,%2,%3};"               \
        : "+f"(d0), "+f"(d1), "+f"(d2), "+f"(d3)                              \
        : "r"(a0), "r"(a1), "r"(a2), "r"(a3), "r"(b0), "r"(b1))

#define LDSM4(r0,r1,r2,r3,addr)                                               \
    asm volatile("ldmatrix.sync.aligned.m8n8.x4.shared.b16 {%0,%1,%2,%3}, [%4];" \
        : "=r"(r0), "=r"(r1), "=r"(r2), "=r"(r3) : "r"(addr))

__device__ __forceinline__ void split2(float v, __nv_bfloat16& h, __nv_bfloat16& l) {
    h = __float2bfloat16_rn(v);
    l = __float2bfloat16_rn(v - __bfloat162float(h));
}

// fast: one packed cvt for hi, bit-trick residuals, one packed cvt for lo.
__device__ __forceinline__ void splitpack2(float x, float y,
                                           uint32_t& hp, uint32_t& lp) {
    asm("cvt.rn.bf16x2.f32 %0, %1, %2;" : "=r"(hp) : "f"(y), "f"(x));
    const float xh = __int_as_float(hp << 16);
    const float yh = __int_as_float(hp & 0xffff0000u);
    asm("cvt.rn.bf16x2.f32 %0, %1, %2;" : "=r"(lp) : "f"(y - yh), "f"(x - xh));
}

// 2^x (input already in log2 domain)
__device__ __forceinline__ float fexp2(float x) {
    x = fmaxf(x, -125.0f);
    float t = x + 12582912.0f;
    int   n = __float_as_int(t) - 0x4B400000;
    float f = x - (t - 12582912.0f);
    float p = 1.33335581e-3f;
    p = fmaf(p, f, 9.61812911e-3f);
    p = fmaf(p, f, 5.55041086e-2f);
    p = fmaf(p, f, 2.40226512e-1f);
    p = fmaf(p, f, 6.93147182e-1f);
    p = fmaf(p, f, 1.0f);
    return p * __int_as_float((n + 127) << 23);
}

// ============================ W transpose+split =============================
__global__ void wsplit_kernel(const float* __restrict__ W1,
                              const float* __restrict__ W2, int which)
{
    __shared__ float tile[32][33];
    const int N = which ? DIM : NQKV;
    __nv_bfloat16* wh = which ? g_qh : (__nv_bfloat16*)g_attn;
    __nv_bfloat16* wl = which ? g_ql : ((__nv_bfloat16*)g_attn + WSPLIT_ELEMS);
    const int s = blockIdx.z;
    const float* __restrict__ W = s ? W2 : W1;
    const int n0 = blockIdx.x * 32;
    const int k0 = blockIdx.y * 32;
    const int tx = threadIdx.x, ty = threadIdx.y;
    #pragma unroll
    for (int j = 0; j < 4; j++)
        tile[ty + j * 8][tx] = W[(size_t)(k0 + ty + j * 8) * N + n0 + tx];
    __syncthreads();
    #pragma unroll
    for (int j = 0; j < 4; j++) {
        float v = tile[tx][ty + j * 8];
        __nv_bfloat16 h, l;
        split2(v, h, l);
        size_t o = ((size_t)s * N + n0 + ty + j * 8) * KDIM + k0 + tx;
        wh[o] = h;
        wl[o] = l;
    }
}

// ============================ HMMA GEMM (128x128, 2m x 4n warps) ============
#define ROWB   80
#define OFF_AH 0
#define OFF_AL (128*ROWB)          // 10240
#define OFF_BH (2*128*ROWB)        // 20480
#define OFF_BL (3*128*ROWB)        // 30720
#define STAGEB (4*128*ROWB)        // 40960
#define GEMM_SMEM (2*STAGEB)       // 81920
#define HLOFF  10240

#define DECL_ACC(mt,nt) \
    float c##mt##nt##0 = 0.f, c##mt##nt##1 = 0.f, c##mt##nt##2 = 0.f, c##mt##nt##3 = 0.f

#define MMA3(mt,nt) \
    MMA16816(c##mt##nt##0, c##mt##nt##1, c##mt##nt##2, c##mt##nt##3,          \
             ah0, ah1, ah2, ah3, bh##nt##0, bh##nt##1);                       \
    MMA16816(c##mt##nt##0, c##mt##nt##1, c##mt##nt##2, c##mt##nt##3,          \
             ah0, ah1, ah2, ah3, bl##nt##0, bl##nt##1);                       \
    MMA16816(c##mt##nt##0, c##mt##nt##1, c##mt##nt##2, c##mt##nt##3,          \
             al0, al1, al2, al3, bh##nt##0, bh##nt##1)

#define MMA_MT(mt) do {                                                       \
    uint32_t ah0, ah1, ah2, ah3, al0, al1, al2, al3;                          \
    LDSM4(ah0, ah1, ah2, ah3, aA0 + (mt) * (16 * ROWB) + ko);                 \
    LDSM4(al0, al1, al2, al3, aA0 + (mt) * (16 * ROWB) + ko + HLOFF);         \
    MMA3(mt,0); MMA3(mt,1); MMA3(mt,2); MMA3(mt,3);                           \
} while (0)

#define EPILOG(mt,nt) do {                                                    \
    const int row0 = m0 + wm * 64 + (mt) * 16 + g;                            \
    const int colg = n0 + wn * 32 + (nt) * 8 + 2 * tg;                        \
    const float e0 = c##mt##nt##0, e1 = c##mt##nt##1;                         \
    const float e2 = c##mt##nt##2, e3 = c##mt##nt##3;                         \
    if (mode == 0) {                                                          \
        const int t3  = colg / DIM;                                           \
        const int rem = colg - t3 * DIM;                                      \
        const int h   = rem >> 6;                                             \
        const int d0  = rem & 63;                                             \
        const int m1_ = row0,     b1_ = m1_ >> 10, nq1 = m1_ & (NSEQ - 1);    \
        const int m2_ = row0 + 8, b2_ = m2_ >> 10, nq2 = m2_ & (NSEQ - 1);    \
        if (t3 == 2) {                                                        \
            const size_t vb1 = (((size_t)(s * NB + b1_) * NH + h) * DH + d0) * NSEQ + nq1; \
            const size_t vb2 = (((size_t)(s * NB + b2_) * NH + h) * DH + d0) * NSEQ + nq2; \
            __nv_bfloat16 h_, l_;                                             \
            split2(e0, h_, l_); g_vh[vb1] = h_;        g_vl[vb1] = l_;        \
            split2(e1, h_, l_); g_vh[vb1 + NSEQ] = h_; g_vl[vb1 + NSEQ] = l_; \
            split2(e2, h_, l_); g_vh[vb2] = h_;        g_vl[vb2] = l_;        \
            split2(e3, h_, l_); g_vh[vb2 + NSEQ] = h_; g_vl[vb2 + NSEQ] = l_; \
        } else {                                                              \
            const float sc_ = (t3 == 0) ? QSC2 : 1.0f;                        \
            __nv_bfloat16* dh = (t3 == 0) ? g_qh : g_kh;                      \
            __nv_bfloat16* dl = (t3 == 0) ? g_ql : g_kl;                      \
            uint32_t hp_, lp_;                                                \
            const size_t i1 = ((((size_t)(s * NB + b1_) * NH + h) * NSEQ + nq1) * DH + d0); \
            const size_t i2 = ((((size_t)(s * NB + b2_) * NH + h) * NSEQ + nq2) * DH + d0); \
            splitpack2(e0 * sc_, e1 * sc_, hp_, lp_);                         \
            *(uint32_t*)(dh + i1) = hp_; *(uint32_t*)(dl + i1) = lp_;         \
            splitpack2(e2 * sc_, e3 * sc_, hp_, lp_);                         \
            *(uint32_t*)(dh + i2) = hp_; *(uint32_t*)(dl + i2) = lp_;         \
        }                                                                     \
    } else {                                                                  \
        const float* bias = s ? bias2 : bias1;                                \
        const float bx = bias[colg], by = bias[colg + 1];                     \
        *(float2*)(out + ((size_t)s * MTOT + row0) * DIM + colg)              \
            = make_float2(e0 + bx, e1 + by);                                  \
        *(float2*)(out + ((size_t)s * MTOT + row0 + 8) * DIM + colg)          \
            = make_float2(e2 + bx, e3 + by);                                  \
    }                                                                         \
} while (0)

#define STAGE_LOAD_A(cc) do {                                                 \
    const float* _p = pA0 + (cc) * KC;                                        \
    _Pragma("unroll")                                                         \
    for (int i4 = 0; i4 < 4; i4++) {                                          \
        float4 v = *(const float4*)(_p + i4 * 4);                             \
        if (mode == 1) {                                                      \
            float4 w = *(const float4*)(pA1 + (cc) * KC + i4 * 4);            \
            v.x += w.x; v.y += w.y; v.z += w.z; v.w += w.w;                   \
        }                                                                     \
        ar[i4 * 4 + 0] = v.x; ar[i4 * 4 + 1] = v.y;                           \
        ar[i4 * 4 + 2] = v.z; ar[i4 * 4 + 3] = v.w;                           \
    }                                                                         \
} while (0)

// B staging via cp.async (pre-split bf16 source), 64B per thread per chunk
#define STAGE_CP_B(cc) do {                                                   \
    const uint32_t bd_ = sb + ((uint32_t)((cc) & 1)) * STAGEB                 \
                        + (uint32_t)(brow * ROWB + bseg * 2);                 \
    cpasync16(bd_ + OFF_BH,      pBh + (cc) * KC);                            \
    cpasync16(bd_ + OFF_BH + 16, pBh + (cc) * KC + 8);                        \
    cpasync16(bd_ + OFF_BL,      pBl + (cc) * KC);                            \
    cpasync16(bd_ + OFF_BL + 16, pBl + (cc) * KC + 8);                        \
} while (0)

__global__ void __launch_bounds__(256, 2) hmma_gemm_kernel(
    const float* __restrict__ A1g, const float* __restrict__ A2g,
    int Ntot, int mode,
    const float* __restrict__ bias1, const float* __restrict__ bias2,
    float* __restrict__ out)
{
    extern __shared__ __align__(16) char smc[];
    const uint32_t sb = s2u(smc);
    const int tid  = threadIdx.x;
    const int lane = tid & 31;
    const int warp = tid >> 5;
    const int wm   = warp >> 2;
    const int wn   = warp & 3;
    const int g    = lane >> 2;
    const int tg   = lane & 3;
    const int s    = blockIdx.z;
    const int m0   = blockIdx.y * 128;
    const int n0   = blockIdx.x * 128;

    const int arow = tid >> 1;
    const int akb  = (tid & 1) * 16;
    const float* pA0;
    const float* pA1 = nullptr;
    if (mode == 0) {
        const float* Ag = s ? A2g : A1g;
        pA0 = Ag + (size_t)(m0 + arow) * KDIM + akb;
    } else {
        const size_t per = (size_t)MTOT * KDIM;
        pA0 = g_attn + (size_t)(2 * s) * per + (size_t)(m0 + arow) * KDIM + akb;
        pA1 = pA0 + per;
    }

    const int brow = tid >> 1;
    const int bseg = (tid & 1) * 16;
    const __nv_bfloat16* pBh;
    const __nv_bfloat16* pBl;
    if (mode == 0) {
        pBh = (const __nv_bfloat16*)g_attn
            + ((size_t)s * NQKV + n0 + brow) * KDIM + bseg;
        pBl = pBh + WSPLIT_ELEMS;
    } else {
        const size_t o = ((size_t)s * DIM + n0 + brow) * KDIM + bseg;
        pBh = g_qh + o;
        pBl = g_ql + o;
    }

    const uint32_t aA0 = sb + OFF_AH
        + (uint32_t)((wm * 64 + (lane & 15)) * ROWB + (lane >> 4) * 16);
    const int bro = (lane & 7) + ((lane >> 4) << 3);
    const uint32_t aB0 = sb + OFF_BH
        + (uint32_t)((wn * 32 + bro) * ROWB + ((lane >> 3) & 1) * 16);
    const uint32_t aB1 = aB0 + 16 * ROWB;

    DECL_ACC(0,0); DECL_ACC(0,1); DECL_ACC(0,2); DECL_ACC(0,3);
    DECL_ACC(1,0); DECL_ACC(1,1); DECL_ACC(1,2); DECL_ACC(1,3);
    DECL_ACC(2,0); DECL_ACC(2,1); DECL_ACC(2,2); DECL_ACC(2,3);
    DECL_ACC(3,0); DECL_ACC(3,1); DECL_ACC(3,2); DECL_ACC(3,3);

    float ar[16];
    STAGE_LOAD_A(0);
    STAGE_CP_B(0);
    CP_COMMIT();

    for (int c = 0; c < NCH; c++) {
        {
            char* adst = smc + (c & 1) * STAGEB + arow * ROWB + akb * 2;
            #pragma unroll
            for (int i = 0; i < 8; i++) {
                uint32_t hp, lp;
                splitpack2(ar[2 * i], ar[2 * i + 1], hp, lp);
                *(uint32_t*)(adst + OFF_AH + i * 4) = hp;
                *(uint32_t*)(adst + OFF_AL + i * 4) = lp;
            }
        }
        CP_WAIT(0);        // B(c) landed
        __syncthreads();   // A(c) visible; all warps done with buf (c+1)&1

        if (c + 1 < NCH) {
            STAGE_LOAD_A(c + 1);
            STAGE_CP_B(c + 1);
            CP_COMMIT();
        }

        const uint32_t boff = (uint32_t)((c & 1) * STAGEB);
        #pragma unroll
        for (int kk = 0; kk < 2; kk++) {
            const uint32_t ko = boff + kk * 32;
            uint32_t bh00, bh01, bh10, bh11, bl00, bl01, bl10, bl11;
            uint32_t bh20, bh21, bh30, bh31, bl20, bl21, bl30, bl31;
            LDSM4(bh00, bh01, bh10, bh11, aB0 + ko);
            LDSM4(bl00, bl01, bl10, bl11, aB0 + ko + HLOFF);
            LDSM4(bh20, bh21, bh30, bh31, aB1 + ko);
            LDSM4(bl20, bl21, bl30, bl31, aB1 + ko + HLOFF);
            MMA_MT(0);
            MMA_MT(1);
            MMA_MT(2);
            MMA_MT(3);
        }
    }

    EPILOG(0,0); EPILOG(0,1); EPILOG(0,2); EPILOG(0,3);
    EPILOG(1,0); EPILOG(1,1); EPILOG(1,2); EPILOG(1,3);
    EPILOG(2,0); EPILOG(2,1); EPILOG(2,2); EPILOG(2,3);
    EPILOG(3,0); EPILOG(3,1); EPILOG(3,2); EPILOG(3,3);
}

// ============================ HMMA attention ================================
#define AROWB  144
#define A_VOFF (2*64*AROWB)
#define A_LOFF (64*AROWB)
#define ATT_SMEM (4*64*AROWB)
#define ATT_SMEM2 (2*ATT_SMEM)

#define LOADQ(ks)                                                             \
    uint32_t qh##ks##0, qh##ks##1, qh##ks##2, qh##ks##3;                      \
    uint32_t ql##ks##0, ql##ks##1, ql##ks##2, ql##ks##3;                      \
    do {                                                                      \
        qh##ks##0 = *(const uint32_t*)(Qh0 + (ks)*16 + 2*tg);                 \
        qh##ks##1 = *(const uint32_t*)(Qh1 + (ks)*16 + 2*tg);                 \
        qh##ks##2 = *(const uint32_t*)(Qh0 + (ks)*16 + 8 + 2*tg);             \
        qh##ks##3 = *(const uint32_t*)(Qh1 + (ks)*16 + 8 + 2*tg);             \
        ql##ks##0 = *(const uint32_t*)(Ql0 + (ks)*16 + 2*tg);                 \
        ql##ks##1 = *(const uint32_t*)(Ql1 + (ks)*16 + 2*tg);                 \
        ql##ks##2 = *(const uint32_t*)(Ql0 + (ks)*16 + 8 + 2*tg);             \
        ql##ks##3 = *(const uint32_t*)(Ql1 + (ks)*16 + 8 + 2*tg);             \
    } while (0)

#define ADECL_S(nt) float s##nt##0=0.f, s##nt##1=0.f, s##nt##2=0.f, s##nt##3=0.f
#define ADECL_O(nt) float o##nt##0=0.f, o##nt##1=0.f, o##nt##2=0.f, o##nt##3=0.f
#define ADECL_P(nt) uint32_t pha##nt=0u, phb##nt=0u, pla##nt=0u, plb##nt=0u

#define ASMMA_P(ks,p,na,nb) do {                                              \
    uint32_t kh0,kh1,kh2,kh3, kl0,kl1,kl2,kl3;                                \
    LDSM4(kh0,kh1,kh2,kh3, aK##p + abuf + (ks)*32);                           \
    LDSM4(kl0,kl1,kl2,kl3, aK##p + abuf + A_LOFF + (ks)*32);                  \
    MMA16816(s##na##0,s##na##1,s##na##2,s##na##3,                             \
             qh##ks##0,qh##ks##1,qh##ks##2,qh##ks##3, kh0,kh1);               \
    MMA16816(s##na##0,s##na##1,s##na##2,s##na##3,                             \
             qh##ks##0,qh##ks##1,qh##ks##2,qh##ks##3, kl0,kl1);               \
    MMA16816(s##na##0,s##na##1,s##na##2,s##na##3,                             \
             ql##ks##0,ql##ks##1,ql##ks##2,ql##ks##3, kh0,kh1);               \
    MMA16816(s##nb##0,s##nb##1,s##nb##2,s##nb##3,                             \
             qh##ks##0,qh##ks##1,qh##ks##2,qh##ks##3, kh2,kh3);               \
    MMA16816(s##nb##0,s##nb##1,s##nb##2,s##nb##3,                             \
             qh##ks##0,qh##ks##1,qh##ks##2,qh##ks##3, kl2,kl3);               \
    MMA16816(s##nb##0,s##nb##1,s##nb##2,s##nb##3,                             \
             ql##ks##0,ql##ks##1,ql##ks##2,ql##ks##3, kh2,kh3);               \
} while (0)

#define ASMMA_ALLNT(ks) do {                                                  \
    ASMMA_P(ks,0,0,1); ASMMA_P(ks,1,2,3);                                     \
    ASMMA_P(ks,2,4,5); ASMMA_P(ks,3,6,7); } while (0)

#define AROWMAX(nt) do {                                                      \
    mxA = fmaxf(mxA, fmaxf(s##nt##0, s##nt##1));                              \
    mxB = fmaxf(mxB, fmaxf(s##nt##2, s##nt##3)); } while (0)

#define ASOFT(nt) do {                                                        \
    const float p0_ = fexp2(s##nt##0 - mxA);                                  \
    const float p1_ = fexp2(s##nt##1 - mxA);                                  \
    const float p2_ = fexp2(s##nt##2 - mxB);                                  \
    const float p3_ = fexp2(s##nt##3 - mxB);                                  \
    sumA += p0_ + p1_; sumB += p2_ + p3_;                                     \
    splitpack2(p0_, p1_, pha##nt, pla##nt);                                   \
    splitpack2(p2_, p3_, phb##nt, plb##nt);                                   \
    o##nt##0 *= corrA; o##nt##1 *= corrA;                                     \
    o##nt##2 *= corrB; o##nt##3 *= corrB; } while (0)

#define APV_P(ks,ta,tb,p,na,nb) do {                                          \
    uint32_t vh0,vh1,vh2,vh3, vl0,vl1,vl2,vl3;                                \
    LDSM4(vh0,vh1,vh2,vh3, aV##p + abuf + (ks)*32);                           \
    LDSM4(vl0,vl1,vl2,vl3, aV##p + abuf + A_LOFF + (ks)*32);                  \
    MMA16816(o##na##0,o##na##1,o##na##2,o##na##3,                             \
             pha##ta, phb##ta, pha##tb, phb##tb, vh0,vh1);                    \
    MMA16816(o##na##0,o##na##1,o##na##2,o##na##3,                             \
             pha##ta, phb##ta, pha##tb, phb##tb, vl0,vl1);                    \
    MMA16816(o##na##0,o##na##1,o##na##2,o##na##3,                             \
             pla##ta, plb##ta, pla##tb, plb##tb, vh0,vh1);                    \
    MMA16816(o##nb##0,o##nb##1,o##nb##2,o##nb##3,                             \
             pha##ta, phb##ta, pha##tb, phb##tb, vh2,vh3);                    \
    MMA16816(o##nb##0,o##nb##1,o##nb##2,o##nb##3,                             \
             pha##ta, phb##ta, pha##tb, phb##tb, vl2,vl3);                    \
    MMA16816(o##nb##0,o##nb##1,o##nb##2,o##nb##3,                             \
             pla##ta, plb##ta, pla##tb, plb##tb, vh2,vh3);                    \
} while (0)

#define APVMMA_ALLNT(ks,ta,tb) do {                                           \
    APV_P(ks,ta,tb,0,0,1); APV_P(ks,ta,tb,1,2,3);                             \
    APV_P(ks,ta,tb,2,4,5); APV_P(ks,ta,tb,3,6,7); } while (0)

#define AWRITE(nt) do {                                                       \
    *(float2*)(OgA + (nt)*8 + 2*tg) = make_float2(o##nt##0*invA, o##nt##1*invA); \
    *(float2*)(OgB + (nt)*8 + 2*tg) = make_float2(o##nt##2*invB, o##nt##3*invB); \
} while (0)

// 8 x 16B cp.async per thread: K hi/lo + V hi/lo segments for tile kt_
#define STAGE_CP_KV(kt_) do {                                                 \
    const uint32_t ab_ = ((uint32_t)((kt_) & 1)) * ATT_SMEM;                  \
    const size_t kok_ = (size_t)((kt_) * 64) * DH;                            \
    const int k0_ = (kt_) * 64;                                               \
    cpasync16(kdsu + ab_,                   pKh + kok_);                      \
    cpasync16(kdsu + ab_ + 16,              pKh + kok_ + 8);                  \
    cpasync16(kdsu + ab_ + A_LOFF,          pKl + kok_);                      \
    cpasync16(kdsu + ab_ + A_LOFF + 16,     pKl + kok_ + 8);                  \
    cpasync16(vdsu + ab_,                   pVh + k0_);                       \
    cpasync16(vdsu + ab_ + 16,              pVh + k0_ + 8);                   \
    cpasync16(vdsu + ab_ + A_LOFF,          pVl + k0_);                       \
    cpasync16(vdsu + ab_ + A_LOFF + 16,     pVl + k0_ + 8);                   \
} while (0)

__global__ void __launch_bounds__(256, 1) attn_hmma_kernel()
{
    extern __shared__ __align__(16) char smc[];
    const uint32_t sb = s2u(smc);
    const int tid  = threadIdx.x;
    const int lane = tid & 31;
    const int warp = tid >> 5;
    const int g    = lane >> 2;
    const int tg   = lane & 3;
    const int combo = blockIdx.z;
    const int bh    = blockIdx.y;
    const int q0    = blockIdx.x * 128;
    const int qs    = combo >> 1;
    const int kvs   = ((combo + 1) >> 1) & 1;

    const size_t qoff  = ((size_t)(qs  * NB * NH) + bh) * NSEQ * DH;
    const size_t kvoff = ((size_t)(kvs * NB * NH) + bh) * NSEQ * DH;

    const __nv_bfloat16* Qh0 = g_qh + qoff + (size_t)(q0 + warp * 16 + g) * DH;
    const __nv_bfloat16* Qh1 = Qh0 + 8 * DH;
    const __nv_bfloat16* Ql0 = g_ql + qoff + (size_t)(q0 + warp * 16 + g) * DH;
    const __nv_bfloat16* Ql1 = Ql0 + 8 * DH;
    LOADQ(0); LOADQ(1); LOADQ(2); LOADQ(3);

    ADECL_O(0); ADECL_O(1); ADECL_O(2); ADECL_O(3);
    ADECL_O(4); ADECL_O(5); ADECL_O(6); ADECL_O(7);
    float mA = -1e30f, mB = -1e30f, lA = 0.f, lB = 0.f;

    const int srow = tid >> 2;
    const int sel  = (tid & 3) * 16;
    const __nv_bfloat16* pKh = g_kh + kvoff + (size_t)srow * DH + sel;
    const __nv_bfloat16* pKl = g_kl + kvoff + (size_t)srow * DH + sel;
    const __nv_bfloat16* pVh = g_vh + kvoff + (size_t)srow * NSEQ + sel;
    const __nv_bfloat16* pVl = g_vl + kvoff + (size_t)srow * NSEQ + sel;
    const uint32_t kdsu = sb + (uint32_t)(srow * AROWB + sel * 2);
    const uint32_t vdsu = kdsu + A_VOFF;

    const int bro = (lane & 7) + ((lane >> 4) << 3);
    const uint32_t kb16 = ((lane >> 3) & 1) * 16;
    const uint32_t aK0 = sb + (uint32_t)(bro * AROWB) + kb16;
    const uint32_t aK1 = aK0 + 16 * AROWB;
    const uint32_t aK2 = aK0 + 32 * AROWB;
    const uint32_t aK3 = aK0 + 48 * AROWB;
    const uint32_t aV0 = aK0 + A_VOFF;
    const uint32_t aV1 = aK1 + A_VOFF;
    const uint32_t aV2 = aK2 + A_VOFF;
    const uint32_t aV3 = aK3 + A_VOFF;

    STAGE_CP_KV(0);
    CP_COMMIT();

    for (int kt = 0; kt < NSEQ / 64; kt++) {
        CP_WAIT(0);        // tile kt landed
        __syncthreads();   // visible to all; all done reading buf (kt+1)&1
        if (kt + 1 < NSEQ / 64) {
            STAGE_CP_KV(kt + 1);   // flies during compute of kt
            CP_COMMIT();
        }
        const uint32_t abuf = ((uint32_t)(kt & 1)) * ATT_SMEM;

        ADECL_S(0); ADECL_S(1); ADECL_S(2); ADECL_S(3);
        ADECL_S(4); ADECL_S(5); ADECL_S(6); ADECL_S(7);
        ASMMA_ALLNT(0); ASMMA_ALLNT(1); ASMMA_ALLNT(2); ASMMA_ALLNT(3);

        float mxA = mA, mxB = mB;
        AROWMAX(0); AROWMAX(1); AROWMAX(2); AROWMAX(3);
        AROWMAX(4); AROWMAX(5); AROWMAX(6); AROWMAX(7);
        mxA = fmaxf(mxA, __shfl_xor_sync(0xffffffffu, mxA, 1));
        mxA = fmaxf(mxA, __shfl_xor_sync(0xffffffffu, mxA, 2));
        mxB = fmaxf(mxB, __shfl_xor_sync(0xffffffffu, mxB, 1));
        mxB = fmaxf(mxB, __shfl_xor_sync(0xffffffffu, mxB, 2));
        const float corrA = fexp2(mA - mxA);
        const float corrB = fexp2(mB - mxB);
        float sumA = 0.f, sumB = 0.f;
        ADECL_P(0); ADECL_P(1); ADECL_P(2); ADECL_P(3);
        ADECL_P(4); ADECL_P(5); ADECL_P(6); ADECL_P(7);
        ASOFT(0); ASOFT(1); ASOFT(2); ASOFT(3);
        ASOFT(4); ASOFT(5); ASOFT(6); ASOFT(7);
        sumA += __shfl_xor_sync(0xffffffffu, sumA, 1);
        sumA += __shfl_xor_sync(0xffffffffu, sumA, 2);
        sumB += __shfl_xor_sync(0xffffffffu, sumB, 1);
        sumB += __shfl_xor_sync(0xffffffffu, sumB, 2);
        lA = lA * corrA + sumA;
        lB = lB * corrB + sumB;
        mA = mxA; mB = mxB;

        APVMMA_ALLNT(0,0,1); APVMMA_ALLNT(1,2,3);
        APVMMA_ALLNT(2,4,5); APVMMA_ALLNT(3,6,7);
    }

    const int b = bh / NH, h = bh - (bh / NH) * NH;
    const int row0 = q0 + warp * 16 + g;
    float* OgA = g_attn + ((size_t)(combo * NB + b) * NSEQ + row0) * DIM + h * DH;
    float* OgB = OgA + 8 * DIM;
    const float invA = 1.f / lA, invB = 1.f / lB;
    AWRITE(0); AWRITE(1); AWRITE(2); AWRITE(3);
    AWRITE(4); AWRITE(5); AWRITE(6); AWRITE(7);
}

// ============================ launch ========================================
extern "C" void kernel_launch(void* const* d_in, const int* in_sizes, int n_in,
                              void* d_out, int out_size)
{
    const float* x1    = (const float*)d_in[0];
    const float* x2    = (const float*)d_in[1];
    const float* Wqkv1 = (const float*)d_in[2];
    const float* Wqkv2 = (const float*)d_in[3];
    const float* Wp1   = (const float*)d_in[4];
    const float* bp1   = (const float*)d_in[5];
    const float* Wp2   = (const float*)d_in[6];
    const float* bp2   = (const float*)d_in[7];
    float* out = (float*)d_out;

    cudaFuncSetAttribute(hmma_gemm_kernel,
                         cudaFuncAttributeMaxDynamicSharedMemorySize, GEMM_SMEM);
    cudaFuncSetAttribute(attn_hmma_kernel,
                         cudaFuncAttributeMaxDynamicSharedMemorySize, ATT_SMEM2);

    wsplit_kernel<<<dim3(NQKV / 32, KDIM / 32, 2), dim3(32, 8)>>>(Wqkv1, Wqkv2, 0);

    hmma_gemm_kernel<<<dim3(NQKV / 128, MTOT / 128, 2), 256, GEMM_SMEM>>>(
        x1, x2, NQKV, 0, nullptr, nullptr, nullptr);

    attn_hmma_kernel<<<dim3(8, 24, 4), 256, ATT_SMEM2>>>();

    wsplit_kernel<<<dim3(DIM / 32, KDIM / 32, 2), dim3(32, 8)>>>(Wp1, Wp2, 1);

    hmma_gemm_kernel<<<dim3(DIM / 128, MTOT / 128, 2), 256, GEMM_SMEM>>>(
        nullptr, nullptr, DIM, 1, bp1, bp2, out);
}